// round 1
// baseline (speedup 1.0000x reference)
#include <cuda_runtime.h>
#include <math.h>

#define BM 128
#define BN 128
#define BK 8
#define TM 8
#define TN 8

// ---- scratch (device globals; no runtime allocation allowed) ----
__device__ float g_scores[4L * 2048 * 2048];   // [B,S,S]   67 MB
__device__ float g_attn  [8192L * 1024];       // [B*S,D]   32 MB
__device__ float g_h     [8192L * 1024];       // [B*S,D]   32 MB
__device__ float g_ffn1  [8192L * 4096];       // [B*S,DFF] 128 MB
__device__ float g_ffn2  [8192L * 1024];       // [B*S,D]   32 MB

// EPI: 0 = plain, 1 = acc*scale + mask[col], 2 = gelu(acc + bias[col]), 3 = acc + bias[col]
// TB:  false -> B is [K,N] row-major (NN GEMM); true -> B is [N,K] row-major (NT GEMM)
template<bool TB, int EPI>
__global__ __launch_bounds__(256) void sgemm_kernel(
    const float* __restrict__ A, const float* __restrict__ B, float* __restrict__ C,
    int M, int N, int K,
    long sA, long sB, long sC,
    const float* __restrict__ aux, long sAux, float scale)
{
    const int bz = blockIdx.z;
    A += (long)bz * sA;
    B += (long)bz * sB;
    C += (long)bz * sC;
    const float* auxp = (EPI != 0) ? (aux + (long)bz * sAux) : nullptr;

    __shared__ float As[BK][BM];
    __shared__ float Bs[BK][BN];

    const int tid = threadIdx.x;
    const int tx = tid % 16;          // 16 threads across N
    const int ty = tid / 16;          // 16 threads across M
    const int m0 = blockIdx.y * BM;
    const int n0 = blockIdx.x * BN;

    // A tile load mapping: 128 rows x 8 cols, one float4 per thread
    const int arow = tid >> 1;
    const int acol = (tid & 1) * 4;
    // B tile load mapping
    const int brow = TB ? (tid >> 1) : (tid >> 5);
    const int bcol = TB ? ((tid & 1) * 4) : ((tid & 31) * 4);

    float acc[TM][TN];
    #pragma unroll
    for (int i = 0; i < TM; i++)
        #pragma unroll
        for (int j = 0; j < TN; j++) acc[i][j] = 0.f;

    for (int k0 = 0; k0 < K; k0 += BK) {
        float4 av = *reinterpret_cast<const float4*>(A + (long)(m0 + arow) * K + k0 + acol);
        As[acol + 0][arow] = av.x;
        As[acol + 1][arow] = av.y;
        As[acol + 2][arow] = av.z;
        As[acol + 3][arow] = av.w;

        if (TB) {
            float4 bv = *reinterpret_cast<const float4*>(B + (long)(n0 + brow) * K + k0 + bcol);
            Bs[bcol + 0][brow] = bv.x;
            Bs[bcol + 1][brow] = bv.y;
            Bs[bcol + 2][brow] = bv.z;
            Bs[bcol + 3][brow] = bv.w;
        } else {
            float4 bv = *reinterpret_cast<const float4*>(B + (long)(k0 + brow) * N + n0 + bcol);
            *reinterpret_cast<float4*>(&Bs[brow][bcol]) = bv;
        }
        __syncthreads();

        #pragma unroll
        for (int kk = 0; kk < BK; kk++) {
            float af[TM], bf[TN];
            #pragma unroll
            for (int i = 0; i < TM; i++) af[i] = As[kk][ty * TM + i];
            #pragma unroll
            for (int j = 0; j < TN; j++) bf[j] = Bs[kk][tx * TN + j];
            #pragma unroll
            for (int i = 0; i < TM; i++)
                #pragma unroll
                for (int j = 0; j < TN; j++) acc[i][j] += af[i] * bf[j];
        }
        __syncthreads();
    }

    #pragma unroll
    for (int i = 0; i < TM; i++) {
        const int row = m0 + ty * TM + i;
        #pragma unroll
        for (int j = 0; j < TN; j += 4) {
            const int col = n0 + tx * TN + j;
            float vals[4];
            #pragma unroll
            for (int u = 0; u < 4; u++) {
                float a = acc[i][j + u];
                if (EPI == 1) {
                    a = a * scale + auxp[col + u];
                } else if (EPI == 2) {
                    a += auxp[col + u];
                    a = 0.5f * a * (1.0f + erff(a * 0.70710678118654752f));  // exact GELU
                } else if (EPI == 3) {
                    a += auxp[col + u];
                }
                vals[u] = a;
            }
            float4 v;
            v.x = vals[0]; v.y = vals[1]; v.z = vals[2]; v.w = vals[3];
            *reinterpret_cast<float4*>(C + (long)row * N + col) = v;
        }
    }
}

// Row softmax over S columns; one block per row.
__global__ __launch_bounds__(256) void softmax_kernel(float* __restrict__ s, int S) {
    const long row = blockIdx.x;
    float* p = s + row * (long)S;
    const int tid = threadIdx.x;
    __shared__ float red[256];

    float m = -INFINITY;
    for (int c = tid; c < S; c += 256) m = fmaxf(m, p[c]);
    red[tid] = m; __syncthreads();
    for (int o = 128; o > 0; o >>= 1) {
        if (tid < o) red[tid] = fmaxf(red[tid], red[tid + o]);
        __syncthreads();
    }
    m = red[0];
    __syncthreads();

    float sum = 0.f;
    for (int c = tid; c < S; c += 256) {
        float e = expf(p[c] - m);
        p[c] = e;
        sum += e;
    }
    red[tid] = sum; __syncthreads();
    for (int o = 128; o > 0; o >>= 1) {
        if (tid < o) red[tid] += red[tid + o];
        __syncthreads();
    }
    const float inv = 1.f / red[0];
    for (int c = tid; c < S; c += 256) p[c] *= inv;
}

// out[row] = LayerNorm(x[row] + y[row]) * g + b    (D = 1024, 256 threads x 4)
__global__ __launch_bounds__(256) void addln_kernel(
    const float* __restrict__ x, const float* __restrict__ y,
    const float* __restrict__ g, const float* __restrict__ b,
    float* __restrict__ out, int D)
{
    const long row = blockIdx.x;
    const float* xp = x + row * (long)D;
    const float* yp = y + row * (long)D;
    float* op = out + row * (long)D;
    const int tid = threadIdx.x;

    float v[4];
    float s = 0.f, ss = 0.f;
    #pragma unroll
    for (int i = 0; i < 4; i++) {
        const int c = tid + i * 256;
        const float t = xp[c] + yp[c];
        v[i] = t;
        s += t;
        ss += t * t;
    }
    __shared__ float r1[256], r2[256];
    r1[tid] = s; r2[tid] = ss; __syncthreads();
    for (int o = 128; o > 0; o >>= 1) {
        if (tid < o) { r1[tid] += r1[tid + o]; r2[tid] += r2[tid + o]; }
        __syncthreads();
    }
    const float mean = r1[0] / (float)D;
    const float var  = r2[0] / (float)D - mean * mean;
    const float rs   = rsqrtf(var + 1e-5f);
    #pragma unroll
    for (int i = 0; i < 4; i++) {
        const int c = tid + i * 256;
        op[c] = (v[i] - mean) * rs * g[c] + b[c];
    }
}

extern "C" void kernel_launch(void* const* d_in, const int* in_sizes, int n_in,
                              void* d_out, int out_size)
{
    const float* x    = (const float*)d_in[0];  // [B,S,D]
    const float* mask = (const float*)d_in[1];  // [B,1,S]
    const float* w1   = (const float*)d_in[2];  // [D,DFF]
    const float* b1   = (const float*)d_in[3];  // [DFF]
    const float* w2   = (const float*)d_in[4];  // [DFF,D]
    const float* b2   = (const float*)d_in[5];  // [D]
    const float* g1   = (const float*)d_in[6];
    const float* bt1  = (const float*)d_in[7];
    const float* g2   = (const float*)d_in[8];
    const float* bt2  = (const float*)d_in[9];
    float* out = (float*)d_out;

    float *scores, *attn, *h, *ffn1, *ffn2;
    cudaGetSymbolAddress((void**)&scores, g_scores);
    cudaGetSymbolAddress((void**)&attn,   g_attn);
    cudaGetSymbolAddress((void**)&h,      g_h);
    cudaGetSymbolAddress((void**)&ffn1,   g_ffn1);
    cudaGetSymbolAddress((void**)&ffn2,   g_ffn2);

    const int B = 4, S = 2048, D = 1024, DFF = 4096;
    const float scale = 0.03125f;  // 1/sqrt(1024) exact
    dim3 blk(256);

    // 1) scores[b] = (X_b X_b^T) * scale + mask[b]   (NT GEMM, per batch)
    sgemm_kernel<true, 1><<<dim3(S / BN, S / BM, B), blk>>>(
        x, x, scores, S, S, D,
        (long)S * D, (long)S * D, (long)S * S,
        mask, (long)S, scale);

    // 2) row softmax
    softmax_kernel<<<B * S, 256>>>(scores, S);

    // 3) attn_out[b] = P_b X_b   (NN GEMM, per batch)
    sgemm_kernel<false, 0><<<dim3(D / BN, S / BM, B), blk>>>(
        scores, x, attn, S, D, S,
        (long)S * S, (long)S * D, (long)S * D,
        nullptr, 0, 1.f);

    // 4) h = LN1(x + attn_out)
    addln_kernel<<<B * S, 256>>>(x, attn, g1, bt1, h, D);

    // 5) ffn1 = gelu(h @ w1 + b1)
    sgemm_kernel<false, 2><<<dim3(DFF / BN, (B * S) / BM, 1), blk>>>(
        h, w1, ffn1, B * S, DFF, D, 0, 0, 0, b1, 0, 1.f);

    // 6) ffn2 = ffn1 @ w2 + b2
    sgemm_kernel<false, 3><<<dim3(D / BN, (B * S) / BM, 1), blk>>>(
        ffn1, w2, ffn2, B * S, D, DFF, 0, 0, 0, b2, 0, 1.f);

    // 7) out = LN2(h + ffn2)
    addln_kernel<<<B * S, 256>>>(h, ffn2, g2, bt2, out, D);
}

// round 3
// speedup vs baseline: 2.6360x; 2.6360x over previous
#include <cuda_runtime.h>
#include <cuda_bf16.h>
#include <math.h>
#include <stdint.h>

#define Bb 4
#define Ss 2048
#define Dd 1024
#define Ff 4096

// ---------------- scratch (device globals; no runtime allocation) ----------------
__device__ __align__(1024) float g_scores[(long)Bb*Ss*Ss];
__device__ __align__(1024) float g_attn  [(long)Bb*Ss*Dd];
__device__ __align__(1024) float g_h     [(long)Bb*Ss*Dd];
__device__ __align__(1024) float g_ffn2  [(long)Bb*Ss*Dd];
__device__ __align__(1024) __nv_bfloat16 g_Xh [(long)Bb*Ss*Dd], g_Xl [(long)Bb*Ss*Dd];
__device__ __align__(1024) __nv_bfloat16 g_XTh[(long)Bb*Dd*Ss], g_XTl[(long)Bb*Dd*Ss];
__device__ __align__(1024) __nv_bfloat16 g_Ph [(long)Bb*Ss*Ss], g_Pl [(long)Bb*Ss*Ss];
__device__ __align__(1024) __nv_bfloat16 g_Hh [(long)Bb*Ss*Dd], g_Hl [(long)Bb*Ss*Dd];
__device__ __align__(1024) __nv_bfloat16 g_W1h[(long)Ff*Dd],    g_W1l[(long)Ff*Dd];
__device__ __align__(1024) __nv_bfloat16 g_W2h[(long)Dd*Ff],    g_W2l[(long)Dd*Ff];
__device__ __align__(1024) __nv_bfloat16 g_Fh [(long)Bb*Ss*Ff], g_Fl [(long)Bb*Ss*Ff];

// ---------------- GEMM tiling ----------------
#define BM 128
#define BN 128
#define BK 32            // bf16 elems per k-chunk; 64 bytes per smem row
#define NTH 256

#define OFF_AH 0
#define OFF_AL (BM*64)
#define OFF_BH (2*BM*64)
#define OFF_BL (2*BM*64 + BN*64)
#define STAGE_BYTES (2*BM*64 + 2*BN*64)   // 32768
#define SMEM_SZ (2*STAGE_BYTES)           // 65536

// ---------------- PTX helpers (baseline ISA only; no tcgen05) ----------------
__device__ __forceinline__ uint32_t swz(uint32_t o) { return o ^ ((o >> 3) & 0x30); }

__device__ __forceinline__ void cp16(uint32_t s, const void* g) {
    asm volatile("cp.async.cg.shared.global [%0], [%1], 16;" :: "r"(s), "l"(g));
}

__device__ __forceinline__ void ldm4(uint32_t* r, uint32_t a) {
    asm volatile("ldmatrix.sync.aligned.m8n8.x4.shared.b16 {%0,%1,%2,%3}, [%4];"
        : "=r"(r[0]), "=r"(r[1]), "=r"(r[2]), "=r"(r[3]) : "r"(a));
}

__device__ __forceinline__ void mma16816(float* c, const uint32_t* a, const uint32_t* b) {
    asm volatile(
        "mma.sync.aligned.m16n8k16.row.col.f32.bf16.bf16.f32 "
        "{%0,%1,%2,%3},{%4,%5,%6,%7},{%8,%9},{%0,%1,%2,%3};"
        : "+f"(c[0]), "+f"(c[1]), "+f"(c[2]), "+f"(c[3])
        : "r"(a[0]), "r"(a[1]), "r"(a[2]), "r"(a[3]), "r"(b[0]), "r"(b[1]));
}

// ---------------- stage loader: 8 x cp.async(16B) per thread ----------------
__device__ __forceinline__ void load_stage(
    uint32_t sb,
    const __nv_bfloat16* __restrict__ Ah, const __nv_bfloat16* __restrict__ Al,
    const __nv_bfloat16* __restrict__ Bh, const __nv_bfloat16* __restrict__ Bl,
    int tid, int m0, int n0, int K, int k0)
{
    const int row = tid >> 1;
    const int cb  = (tid & 1) * 32;           // byte col within 64B row
    const uint32_t so = (uint32_t)row * 64u + (uint32_t)cb;
    const char* ga_h = (const char*)(Ah + (long)(m0 + row) * K + k0) + cb;
    const char* ga_l = (const char*)(Al + (long)(m0 + row) * K + k0) + cb;
    const char* gb_h = (const char*)(Bh + (long)(n0 + row) * K + k0) + cb;
    const char* gb_l = (const char*)(Bl + (long)(n0 + row) * K + k0) + cb;
    cp16(sb + OFF_AH + swz(so),      ga_h);
    cp16(sb + OFF_AH + swz(so + 16), ga_h + 16);
    cp16(sb + OFF_AL + swz(so),      ga_l);
    cp16(sb + OFF_AL + swz(so + 16), ga_l + 16);
    cp16(sb + OFF_BH + swz(so),      gb_h);
    cp16(sb + OFF_BH + swz(so + 16), gb_h + 16);
    cp16(sb + OFF_BL + swz(so),      gb_l);
    cp16(sb + OFF_BL + swz(so + 16), gb_l + 16);
}

// EPI: 0 plain fp32, 1 acc*scale+mask[col] fp32, 2 gelu(acc+bias[col])->bf16 split, 3 acc+bias[col] fp32
template<int EPI, bool SPLIT_OUT>
__global__ __launch_bounds__(NTH, 2)
void gemm_tc(
    const __nv_bfloat16* __restrict__ Ah, const __nv_bfloat16* __restrict__ Al,
    const __nv_bfloat16* __restrict__ Bh, const __nv_bfloat16* __restrict__ Bl,
    float* __restrict__ C, __nv_bfloat16* __restrict__ Ch, __nv_bfloat16* __restrict__ Cl,
    int M, int N, int K, long sA, long sB, long sC,
    const float* __restrict__ aux, long sAux, float scale)
{
    extern __shared__ char dsm[];
    const uint32_t data = (uint32_t)__cvta_generic_to_shared(dsm);

    const int tid = threadIdx.x, wid = tid >> 5, lane = tid & 31;
    const int wm = wid >> 1;        // 0..3 -> M
    const int wn = wid & 1;         // 0..1 -> N
    const int bz = blockIdx.z;
    Ah += bz * sA; Al += bz * sA;
    Bh += bz * sB; Bl += bz * sB;
    const int m0 = blockIdx.y * BM, n0 = blockIdx.x * BN;

    float acc[2][8][4];
    #pragma unroll
    for (int i = 0; i < 2; i++)
        #pragma unroll
        for (int j = 0; j < 8; j++)
            #pragma unroll
            for (int q = 0; q < 4; q++) acc[i][j][q] = 0.f;

    const int nch = K / BK;
    load_stage(data, Ah, Al, Bh, Bl, tid, m0, n0, K, 0);
    asm volatile("cp.async.commit_group;");

    for (int i = 0; i < nch; i++) {
        const uint32_t sb = data + (uint32_t)(i & 1) * STAGE_BYTES;
        if (i + 1 < nch) {
            load_stage(data + (uint32_t)((i + 1) & 1) * STAGE_BYTES,
                       Ah, Al, Bh, Bl, tid, m0, n0, K, (i + 1) * BK);
            asm volatile("cp.async.commit_group;");
            asm volatile("cp.async.wait_group 1;");
        } else {
            asm volatile("cp.async.wait_group 0;");
        }
        __syncthreads();

        #pragma unroll
        for (int k16 = 0; k16 < 2; k16++) {
            uint32_t ah[2][4], al[2][4], bh[4][4], bl[4][4];
            const uint32_t arow = (uint32_t)(wm * 32 + (lane & 15));
            const uint32_t acol = (uint32_t)(k16 * 32 + (lane >> 4) * 16);
            ldm4(ah[0], sb + OFF_AH + swz(arow * 64 + acol));
            ldm4(ah[1], sb + OFF_AH + swz((arow + 16) * 64 + acol));
            ldm4(al[0], sb + OFF_AL + swz(arow * 64 + acol));
            ldm4(al[1], sb + OFF_AL + swz((arow + 16) * 64 + acol));
            const uint32_t brow = (uint32_t)(wn * 64 + (lane & 7) + (lane >> 4) * 8);
            const uint32_t bcol = (uint32_t)(k16 * 32 + ((lane >> 3) & 1) * 16);
            #pragma unroll
            for (int j = 0; j < 4; j++) {
                ldm4(bh[j], sb + OFF_BH + swz((brow + j * 16) * 64 + bcol));
                ldm4(bl[j], sb + OFF_BL + swz((brow + j * 16) * 64 + bcol));
            }
            #pragma unroll
            for (int mi = 0; mi < 2; mi++)
                #pragma unroll
                for (int nj = 0; nj < 8; nj++) {
                    const uint32_t* bhp = &bh[nj >> 1][(nj & 1) * 2];
                    const uint32_t* blp = &bl[nj >> 1][(nj & 1) * 2];
                    mma16816(acc[mi][nj], ah[mi], bhp);
                    mma16816(acc[mi][nj], ah[mi], blp);
                    mma16816(acc[mi][nj], al[mi], bhp);
                }
        }
        __syncthreads();
    }

    // ---------------- epilogue from register accumulators ----------------
    const float* auxp = (EPI != 0) ? (aux + bz * sAux) : nullptr;
    if (!SPLIT_OUT && C) C += bz * sC;
    if (SPLIT_OUT) { Ch += bz * sC; Cl += bz * sC; }

    #pragma unroll
    for (int mi = 0; mi < 2; mi++) {
        const int r0 = m0 + wm * 32 + mi * 16 + (lane >> 2);
        #pragma unroll
        for (int nj = 0; nj < 8; nj++) {
            const int c0 = n0 + wn * 64 + nj * 8 + (lane & 3) * 2;
            float v[4] = { acc[mi][nj][0], acc[mi][nj][1], acc[mi][nj][2], acc[mi][nj][3] };
            #pragma unroll
            for (int q = 0; q < 4; q++) {
                const int col = c0 + (q & 1);
                float a = v[q];
                if (EPI == 1)      a = a * scale + __ldg(&auxp[col]);
                else if (EPI == 2) { a += __ldg(&auxp[col]);
                                     a = 0.5f * a * (1.0f + erff(a * 0.70710678118654752f)); }
                else if (EPI == 3) a += __ldg(&auxp[col]);
                v[q] = a;
            }
            if (!SPLIT_OUT) {
                float2 lo; lo.x = v[0]; lo.y = v[1];
                float2 hi; hi.x = v[2]; hi.y = v[3];
                *reinterpret_cast<float2*>(C + (long)r0 * N + c0)       = lo;
                *reinterpret_cast<float2*>(C + (long)(r0 + 8) * N + c0) = hi;
            } else {
                __nv_bfloat162 h01, h23, l01, l23;
                h01.x = __float2bfloat16(v[0]); h01.y = __float2bfloat16(v[1]);
                h23.x = __float2bfloat16(v[2]); h23.y = __float2bfloat16(v[3]);
                l01.x = __float2bfloat16(v[0] - __bfloat162float(h01.x));
                l01.y = __float2bfloat16(v[1] - __bfloat162float(h01.y));
                l23.x = __float2bfloat16(v[2] - __bfloat162float(h23.x));
                l23.y = __float2bfloat16(v[3] - __bfloat162float(h23.y));
                *reinterpret_cast<__nv_bfloat162*>(Ch + (long)r0 * N + c0)       = h01;
                *reinterpret_cast<__nv_bfloat162*>(Ch + (long)(r0 + 8) * N + c0) = h23;
                *reinterpret_cast<__nv_bfloat162*>(Cl + (long)r0 * N + c0)       = l01;
                *reinterpret_cast<__nv_bfloat162*>(Cl + (long)(r0 + 8) * N + c0) = l23;
            }
        }
    }
}

// ---------------- elementwise split: fp32 -> bf16 hi/lo ----------------
__global__ __launch_bounds__(256) void split_kernel(
    const float* __restrict__ in, __nv_bfloat16* __restrict__ oh,
    __nv_bfloat16* __restrict__ ol, long n)
{
    long i = ((long)blockIdx.x * blockDim.x + threadIdx.x) * 4;
    if (i >= n) return;
    float4 x = *reinterpret_cast<const float4*>(in + i);
    float vv[4] = { x.x, x.y, x.z, x.w };
    __nv_bfloat162 h01, h23, l01, l23;
    __nv_bfloat16 h[4];
    #pragma unroll
    for (int k = 0; k < 4; k++) h[k] = __float2bfloat16(vv[k]);
    h01.x = h[0]; h01.y = h[1]; h23.x = h[2]; h23.y = h[3];
    l01.x = __float2bfloat16(vv[0] - __bfloat162float(h[0]));
    l01.y = __float2bfloat16(vv[1] - __bfloat162float(h[1]));
    l23.x = __float2bfloat16(vv[2] - __bfloat162float(h[2]));
    l23.y = __float2bfloat16(vv[3] - __bfloat162float(h[3]));
    *reinterpret_cast<__nv_bfloat162*>(oh + i)     = h01;
    *reinterpret_cast<__nv_bfloat162*>(oh + i + 2) = h23;
    *reinterpret_cast<__nv_bfloat162*>(ol + i)     = l01;
    *reinterpret_cast<__nv_bfloat162*>(ol + i + 2) = l23;
}

// ---------------- transpose + split: fp32 [R,C] -> bf16 hi/lo [C,R] ----------------
__global__ __launch_bounds__(256) void tsplit_kernel(
    const float* __restrict__ in, __nv_bfloat16* __restrict__ oh,
    __nv_bfloat16* __restrict__ ol, int R, int C, long sIn, long sOut)
{
    __shared__ float t[32][33];
    in += blockIdx.z * sIn; oh += blockIdx.z * sOut; ol += blockIdx.z * sOut;
    const int c0 = blockIdx.x * 32, r0 = blockIdx.y * 32;
    const int tx = threadIdx.x, ty = threadIdx.y;  // 32 x 8
    #pragma unroll
    for (int k = 0; k < 4; k++)
        t[ty + 8*k][tx] = in[(long)(r0 + ty + 8*k) * C + c0 + tx];
    __syncthreads();
    #pragma unroll
    for (int k = 0; k < 4; k++) {
        const float v = t[tx][ty + 8*k];
        const __nv_bfloat16 h = __float2bfloat16(v);
        const long o = (long)(c0 + ty + 8*k) * R + r0 + tx;
        oh[o] = h;
        ol[o] = __float2bfloat16(v - __bfloat162float(h));
    }
}

// ---------------- row softmax over S cols; writes bf16 hi/lo split ----------------
__global__ __launch_bounds__(256) void softmax_kernel(
    const float* __restrict__ s, __nv_bfloat16* __restrict__ ph,
    __nv_bfloat16* __restrict__ pl, int S)
{
    const long row = blockIdx.x;
    const float* p = s + row * (long)S;
    __nv_bfloat16* oh = ph + row * (long)S;
    __nv_bfloat16* ol = pl + row * (long)S;
    const int tid = threadIdx.x;
    __shared__ float red[256];
    __shared__ float ex[2048];

    float m = -INFINITY;
    for (int c = tid; c < S; c += 256) m = fmaxf(m, p[c]);
    red[tid] = m; __syncthreads();
    for (int o = 128; o > 0; o >>= 1) {
        if (tid < o) red[tid] = fmaxf(red[tid], red[tid + o]);
        __syncthreads();
    }
    m = red[0];
    __syncthreads();

    float sum = 0.f;
    for (int c = tid; c < S; c += 256) {
        const float e = expf(p[c] - m);
        ex[c] = e;
        sum += e;
    }
    red[tid] = sum; __syncthreads();
    for (int o = 128; o > 0; o >>= 1) {
        if (tid < o) red[tid] += red[tid + o];
        __syncthreads();
    }
    const float inv = 1.f / red[0];
    for (int c = tid; c < S; c += 256) {
        const float v = ex[c] * inv;
        const __nv_bfloat16 h = __float2bfloat16(v);
        oh[c] = h;
        ol[c] = __float2bfloat16(v - __bfloat162float(h));
    }
}

// ---------------- residual + LayerNorm (D=1024), optional bf16 split out ----------------
template<bool DO_SPLIT>
__global__ __launch_bounds__(256) void addln_kernel(
    const float* __restrict__ x, const float* __restrict__ y,
    const float* __restrict__ g, const float* __restrict__ b,
    float* __restrict__ out, __nv_bfloat16* __restrict__ oh,
    __nv_bfloat16* __restrict__ ol, int D)
{
    const long row = blockIdx.x;
    const float* xp = x + row * (long)D;
    const float* yp = y + row * (long)D;
    const int tid = threadIdx.x;

    float v[4];
    float s = 0.f, ss = 0.f;
    #pragma unroll
    for (int i = 0; i < 4; i++) {
        const int c = tid + i * 256;
        const float t = xp[c] + yp[c];
        v[i] = t; s += t; ss += t * t;
    }
    __shared__ float r1[256], r2[256];
    r1[tid] = s; r2[tid] = ss; __syncthreads();
    for (int o = 128; o > 0; o >>= 1) {
        if (tid < o) { r1[tid] += r1[tid + o]; r2[tid] += r2[tid + o]; }
        __syncthreads();
    }
    const float mean = r1[0] / (float)D;
    const float var  = r2[0] / (float)D - mean * mean;
    const float rs   = rsqrtf(var + 1e-5f);
    #pragma unroll
    for (int i = 0; i < 4; i++) {
        const int c = tid + i * 256;
        const float o = (v[i] - mean) * rs * g[c] + b[c];
        out[row * (long)D + c] = o;
        if (DO_SPLIT) {
            const __nv_bfloat16 h = __float2bfloat16(o);
            oh[row * (long)D + c] = h;
            ol[row * (long)D + c] = __float2bfloat16(o - __bfloat162float(h));
        }
    }
}

extern "C" void kernel_launch(void* const* d_in, const int* in_sizes, int n_in,
                              void* d_out, int out_size)
{
    const float* x    = (const float*)d_in[0];
    const float* mask = (const float*)d_in[1];
    const float* w1   = (const float*)d_in[2];
    const float* b1   = (const float*)d_in[3];
    const float* w2   = (const float*)d_in[4];
    const float* b2   = (const float*)d_in[5];
    const float* g1   = (const float*)d_in[6];
    const float* bt1  = (const float*)d_in[7];
    const float* g2   = (const float*)d_in[8];
    const float* bt2  = (const float*)d_in[9];
    float* out = (float*)d_out;

    float *scores, *attn, *h, *ffn2;
    __nv_bfloat16 *Xh, *Xl, *XTh, *XTl, *Ph, *Pl, *Hh, *Hl, *W1h, *W1l, *W2h, *W2l, *Fh, *Fl;
    cudaGetSymbolAddress((void**)&scores, g_scores);
    cudaGetSymbolAddress((void**)&attn,   g_attn);
    cudaGetSymbolAddress((void**)&h,      g_h);
    cudaGetSymbolAddress((void**)&ffn2,   g_ffn2);
    cudaGetSymbolAddress((void**)&Xh,  g_Xh);  cudaGetSymbolAddress((void**)&Xl,  g_Xl);
    cudaGetSymbolAddress((void**)&XTh, g_XTh); cudaGetSymbolAddress((void**)&XTl, g_XTl);
    cudaGetSymbolAddress((void**)&Ph,  g_Ph);  cudaGetSymbolAddress((void**)&Pl,  g_Pl);
    cudaGetSymbolAddress((void**)&Hh,  g_Hh);  cudaGetSymbolAddress((void**)&Hl,  g_Hl);
    cudaGetSymbolAddress((void**)&W1h, g_W1h); cudaGetSymbolAddress((void**)&W1l, g_W1l);
    cudaGetSymbolAddress((void**)&W2h, g_W2h); cudaGetSymbolAddress((void**)&W2l, g_W2l);
    cudaGetSymbolAddress((void**)&Fh,  g_Fh);  cudaGetSymbolAddress((void**)&Fl,  g_Fl);

    cudaFuncSetAttribute(gemm_tc<1,false>, cudaFuncAttributeMaxDynamicSharedMemorySize, SMEM_SZ);
    cudaFuncSetAttribute(gemm_tc<0,false>, cudaFuncAttributeMaxDynamicSharedMemorySize, SMEM_SZ);
    cudaFuncSetAttribute(gemm_tc<2,true>,  cudaFuncAttributeMaxDynamicSharedMemorySize, SMEM_SZ);
    cudaFuncSetAttribute(gemm_tc<3,false>, cudaFuncAttributeMaxDynamicSharedMemorySize, SMEM_SZ);

    const int B = Bb, S = Ss, D = Dd, DFF = Ff;
    const float scale = 0.03125f;  // 1/sqrt(1024)
    const long nX = (long)B * S * D;

    // 0) splits / transposes of GEMM operands
    split_kernel<<<(unsigned)(nX / 4 / 256), 256>>>(x, Xh, Xl, nX);
    tsplit_kernel<<<dim3(D/32, S/32, B), dim3(32,8)>>>(x,  XTh, XTl, S, D, (long)S*D, (long)D*S);
    tsplit_kernel<<<dim3(DFF/32, D/32, 1), dim3(32,8)>>>(w1, W1h, W1l, D, DFF, 0, 0);
    tsplit_kernel<<<dim3(D/32, DFF/32, 1), dim3(32,8)>>>(w2, W2h, W2l, DFF, D, 0, 0);

    // 1) scores = (X X^T) * scale + mask   -> fp32
    gemm_tc<1,false><<<dim3(S/BN, S/BM, B), NTH, SMEM_SZ>>>(
        Xh, Xl, Xh, Xl, scores, nullptr, nullptr,
        S, S, D, (long)S*D, (long)S*D, (long)S*S, mask, (long)S, scale);

    // 2) softmax rows -> P split (bf16 hi/lo)
    softmax_kernel<<<B*S, 256>>>(scores, Ph, Pl, S);

    // 3) attn = P X  (B operand = X^T, K-major)  -> fp32
    gemm_tc<0,false><<<dim3(D/BN, S/BM, B), NTH, SMEM_SZ>>>(
        Ph, Pl, XTh, XTl, attn, nullptr, nullptr,
        S, D, S, (long)S*S, (long)D*S, (long)S*D, nullptr, 0, 1.f);

    // 4) h = LN1(x + attn)  (+ H split)
    addln_kernel<true><<<B*S, 256>>>(x, attn, g1, bt1, h, Hh, Hl, D);

    // 5) F = gelu(h @ w1 + b1)  -> bf16 split directly
    gemm_tc<2,true><<<dim3(DFF/BN, (B*S)/BM, 1), NTH, SMEM_SZ>>>(
        Hh, Hl, W1h, W1l, nullptr, Fh, Fl,
        B*S, DFF, D, 0, 0, 0, b1, 0, 1.f);

    // 6) ffn2 = F @ w2 + b2 -> fp32
    gemm_tc<3,false><<<dim3(D/BN, (B*S)/BM, 1), NTH, SMEM_SZ>>>(
        Fh, Fl, W2h, W2l, ffn2, nullptr, nullptr,
        B*S, D, DFF, 0, 0, 0, b2, 0, 1.f);

    // 7) out = LN2(h + ffn2)
    addln_kernel<false><<<B*S, 256>>>(h, ffn2, g2, bt2, out, nullptr, nullptr, D);
}

// round 4
// speedup vs baseline: 3.7572x; 1.4254x over previous
#include <cuda_runtime.h>
#include <cuda_fp16.h>
#include <math.h>
#include <stdint.h>

#define Bb 4
#define Ss 2048
#define Dd 1024
#define Ff 4096

// ---------------- scratch (device globals; no runtime allocation) ----------------
__device__ __align__(1024) float g_scores[(long)Bb*Ss*Ss];
__device__ __align__(1024) float g_attn  [(long)Bb*Ss*Dd];
__device__ __align__(1024) float g_h     [(long)Bb*Ss*Dd];
__device__ __align__(1024) float g_ffn2  [(long)Bb*Ss*Dd];
__device__ __align__(1024) __half g_Xh [(long)Bb*Ss*Dd], g_Xl [(long)Bb*Ss*Dd];
__device__ __align__(1024) __half g_XTh[(long)Bb*Dd*Ss];
__device__ __align__(1024) __half g_Ph [(long)Bb*Ss*Ss], g_Pl [(long)Bb*Ss*Ss];
__device__ __align__(1024) __half g_Hh [(long)Bb*Ss*Dd], g_Hl [(long)Bb*Ss*Dd];
__device__ __align__(1024) __half g_W1h[(long)Ff*Dd];
__device__ __align__(1024) __half g_W2h[(long)Dd*Ff];
__device__ __align__(1024) __half g_Fh [(long)Bb*Ss*Ff], g_Fl [(long)Bb*Ss*Ff];

// ---------------- GEMM tiling ----------------
#define BM 128
#define BN 128
#define BK 32            // fp16 elems per k-chunk; 64 bytes per smem row
#define NTH 256
#define STAGES 3

#define OFF_AH 0
#define OFF_AL (BM*64)
#define OFF_BH (2*BM*64)
#define STAGE_BYTES (3*BM*64)            // 24576
#define SMEM_SZ (STAGES*STAGE_BYTES)     // 73728

// ---------------- PTX helpers (baseline ISA only) ----------------
__device__ __forceinline__ uint32_t swz(uint32_t o) { return o ^ ((o >> 3) & 0x30); }

__device__ __forceinline__ void cp16(uint32_t s, const void* g) {
    asm volatile("cp.async.cg.shared.global [%0], [%1], 16;" :: "r"(s), "l"(g));
}

__device__ __forceinline__ void ldm4(uint32_t* r, uint32_t a) {
    asm volatile("ldmatrix.sync.aligned.m8n8.x4.shared.b16 {%0,%1,%2,%3}, [%4];"
        : "=r"(r[0]), "=r"(r[1]), "=r"(r[2]), "=r"(r[3]) : "r"(a));
}

__device__ __forceinline__ void mma16816(float* c, const uint32_t* a, const uint32_t* b) {
    asm volatile(
        "mma.sync.aligned.m16n8k16.row.col.f32.f16.f16.f32 "
        "{%0,%1,%2,%3},{%4,%5,%6,%7},{%8,%9},{%0,%1,%2,%3};"
        : "+f"(c[0]), "+f"(c[1]), "+f"(c[2]), "+f"(c[3])
        : "r"(a[0]), "r"(a[1]), "r"(a[2]), "r"(a[3]), "r"(b[0]), "r"(b[1]));
}

// ---------------- stage loader: 6 x cp.async(16B) per thread ----------------
__device__ __forceinline__ void load_stage(
    uint32_t sb,
    const __half* __restrict__ Ah, const __half* __restrict__ Al,
    const __half* __restrict__ Bh,
    int tid, int m0, int n0, int K, int k0)
{
    const int row = tid >> 1;
    const int cb  = (tid & 1) * 32;           // byte col within 64B row
    const uint32_t so = (uint32_t)row * 64u + (uint32_t)cb;
    const char* ga_h = (const char*)(Ah + (long)(m0 + row) * K + k0) + cb;
    const char* ga_l = (const char*)(Al + (long)(m0 + row) * K + k0) + cb;
    const char* gb_h = (const char*)(Bh + (long)(n0 + row) * K + k0) + cb;
    cp16(sb + OFF_AH + swz(so),      ga_h);
    cp16(sb + OFF_AH + swz(so + 16), ga_h + 16);
    cp16(sb + OFF_AL + swz(so),      ga_l);
    cp16(sb + OFF_AL + swz(so + 16), ga_l + 16);
    cp16(sb + OFF_BH + swz(so),      gb_h);
    cp16(sb + OFF_BH + swz(so + 16), gb_h + 16);
}

__device__ __forceinline__ void split_h(float v, __half& hi, __half& lo) {
    hi = __float2half_rn(v);
    lo = __float2half_rn(v - __half2float(hi));
}

// EPI: 0 plain fp32, 1 acc*scale+mask[col] fp32, 2 gelu(acc+bias[col])->fp16 split, 3 acc+bias[col] fp32
template<int EPI, bool SPLIT_OUT>
__global__ __launch_bounds__(NTH, 2)
void gemm_tc(
    const __half* __restrict__ Ah, const __half* __restrict__ Al,
    const __half* __restrict__ Bh,
    float* __restrict__ C, __half* __restrict__ Ch, __half* __restrict__ Cl,
    int M, int N, int K, long sA, long sB, long sC,
    const float* __restrict__ aux, long sAux, float scale)
{
    extern __shared__ char dsm[];
    const uint32_t data = (uint32_t)__cvta_generic_to_shared(dsm);

    const int tid = threadIdx.x, wid = tid >> 5, lane = tid & 31;
    const int wm = wid >> 1;        // 0..3 -> M
    const int wn = wid & 1;         // 0..1 -> N
    const int bz = blockIdx.z;
    Ah += bz * sA; Al += bz * sA;
    Bh += bz * sB;
    const int m0 = blockIdx.y * BM, n0 = blockIdx.x * BN;

    float acc[2][8][4];
    #pragma unroll
    for (int i = 0; i < 2; i++)
        #pragma unroll
        for (int j = 0; j < 8; j++)
            #pragma unroll
            for (int q = 0; q < 4; q++) acc[i][j][q] = 0.f;

    const int nch = K / BK;
    load_stage(data, Ah, Al, Bh, tid, m0, n0, K, 0);
    asm volatile("cp.async.commit_group;");
    load_stage(data + STAGE_BYTES, Ah, Al, Bh, tid, m0, n0, K, BK);
    asm volatile("cp.async.commit_group;");

    int sidx = 0;
    for (int i = 0; i < nch; i++) {
        if (i + 2 < nch) {
            const int s2 = (i + 2) % STAGES;
            load_stage(data + (uint32_t)s2 * STAGE_BYTES, Ah, Al, Bh, tid, m0, n0, K, (i + 2) * BK);
            asm volatile("cp.async.commit_group;");
            asm volatile("cp.async.wait_group 2;");
        } else if (i + 1 < nch) {
            asm volatile("cp.async.wait_group 1;");
        } else {
            asm volatile("cp.async.wait_group 0;");
        }
        __syncthreads();

        const uint32_t sb = data + (uint32_t)sidx * STAGE_BYTES;
        sidx = (sidx + 1 == STAGES) ? 0 : sidx + 1;

        #pragma unroll
        for (int k16 = 0; k16 < 2; k16++) {
            uint32_t ah[2][4], al[2][4], bh[4][4];
            const uint32_t arow = (uint32_t)(wm * 32 + (lane & 15));
            const uint32_t acol = (uint32_t)(k16 * 32 + (lane >> 4) * 16);
            ldm4(ah[0], sb + OFF_AH + swz(arow * 64 + acol));
            ldm4(ah[1], sb + OFF_AH + swz((arow + 16) * 64 + acol));
            ldm4(al[0], sb + OFF_AL + swz(arow * 64 + acol));
            ldm4(al[1], sb + OFF_AL + swz((arow + 16) * 64 + acol));
            const uint32_t brow = (uint32_t)(wn * 64 + (lane & 7) + (lane >> 4) * 8);
            const uint32_t bcol = (uint32_t)(k16 * 32 + ((lane >> 3) & 1) * 16);
            #pragma unroll
            for (int j = 0; j < 4; j++)
                ldm4(bh[j], sb + OFF_BH + swz((brow + j * 16) * 64 + bcol));

            #pragma unroll
            for (int mi = 0; mi < 2; mi++)
                #pragma unroll
                for (int nj = 0; nj < 8; nj++) {
                    const uint32_t* bhp = &bh[nj >> 1][(nj & 1) * 2];
                    mma16816(acc[mi][nj], ah[mi], bhp);
                    mma16816(acc[mi][nj], al[mi], bhp);
                }
        }
        __syncthreads();
    }

    // ---------------- epilogue from register accumulators ----------------
    const float* auxp = (EPI != 0) ? (aux + bz * sAux) : nullptr;
    if (!SPLIT_OUT && C) C += bz * sC;
    if (SPLIT_OUT) { Ch += bz * sC; Cl += bz * sC; }

    #pragma unroll
    for (int mi = 0; mi < 2; mi++) {
        const int r0 = m0 + wm * 32 + mi * 16 + (lane >> 2);
        #pragma unroll
        for (int nj = 0; nj < 8; nj++) {
            const int c0 = n0 + wn * 64 + nj * 8 + (lane & 3) * 2;
            float v[4] = { acc[mi][nj][0], acc[mi][nj][1], acc[mi][nj][2], acc[mi][nj][3] };
            #pragma unroll
            for (int q = 0; q < 4; q++) {
                const int col = c0 + (q & 1);
                float a = v[q];
                if (EPI == 1)      a = a * scale + __ldg(&auxp[col]);
                else if (EPI == 2) { a += __ldg(&auxp[col]);
                                     a = 0.5f * a * (1.0f + erff(a * 0.70710678118654752f)); }
                else if (EPI == 3) a += __ldg(&auxp[col]);
                v[q] = a;
            }
            if (!SPLIT_OUT) {
                float2 lo; lo.x = v[0]; lo.y = v[1];
                float2 hi; hi.x = v[2]; hi.y = v[3];
                *reinterpret_cast<float2*>(C + (long)r0 * N + c0)       = lo;
                *reinterpret_cast<float2*>(C + (long)(r0 + 8) * N + c0) = hi;
            } else {
                __half2 h01, h23, l01, l23;
                split_h(v[0], h01.x, l01.x);
                split_h(v[1], h01.y, l01.y);
                split_h(v[2], h23.x, l23.x);
                split_h(v[3], h23.y, l23.y);
                *reinterpret_cast<__half2*>(Ch + (long)r0 * N + c0)       = h01;
                *reinterpret_cast<__half2*>(Ch + (long)(r0 + 8) * N + c0) = h23;
                *reinterpret_cast<__half2*>(Cl + (long)r0 * N + c0)       = l01;
                *reinterpret_cast<__half2*>(Cl + (long)(r0 + 8) * N + c0) = l23;
            }
        }
    }
}

// ---------------- elementwise split: fp32 -> fp16 hi/lo ----------------
__global__ __launch_bounds__(256) void split_kernel(
    const float* __restrict__ in, __half* __restrict__ oh,
    __half* __restrict__ ol, long n)
{
    long i = ((long)blockIdx.x * blockDim.x + threadIdx.x) * 4;
    if (i >= n) return;
    float4 x = *reinterpret_cast<const float4*>(in + i);
    float vv[4] = { x.x, x.y, x.z, x.w };
    __half2 h01, h23, l01, l23;
    split_h(vv[0], h01.x, l01.x);
    split_h(vv[1], h01.y, l01.y);
    split_h(vv[2], h23.x, l23.x);
    split_h(vv[3], h23.y, l23.y);
    *reinterpret_cast<__half2*>(oh + i)     = h01;
    *reinterpret_cast<__half2*>(oh + i + 2) = h23;
    *reinterpret_cast<__half2*>(ol + i)     = l01;
    *reinterpret_cast<__half2*>(ol + i + 2) = l23;
}

// ---------------- transpose: fp32 [R,C] -> fp16 hi [C,R] ----------------
__global__ __launch_bounds__(256) void tsplit_kernel(
    const float* __restrict__ in, __half* __restrict__ oh,
    int R, int C, long sIn, long sOut)
{
    __shared__ float t[32][33];
    in += blockIdx.z * sIn; oh += blockIdx.z * sOut;
    const int c0 = blockIdx.x * 32, r0 = blockIdx.y * 32;
    const int tx = threadIdx.x, ty = threadIdx.y;  // 32 x 8
    #pragma unroll
    for (int k = 0; k < 4; k++)
        t[ty + 8*k][tx] = in[(long)(r0 + ty + 8*k) * C + c0 + tx];
    __syncthreads();
    #pragma unroll
    for (int k = 0; k < 4; k++) {
        const float v = t[tx][ty + 8*k];
        oh[(long)(c0 + ty + 8*k) * R + r0 + tx] = __float2half_rn(v);
    }
}

// ---------------- row softmax over S cols; writes fp16 hi/lo split ----------------
__global__ __launch_bounds__(256) void softmax_kernel(
    const float* __restrict__ s, __half* __restrict__ ph,
    __half* __restrict__ pl, int S)
{
    const long row = blockIdx.x;
    const float* p = s + row * (long)S;
    __half* oh = ph + row * (long)S;
    __half* ol = pl + row * (long)S;
    const int tid = threadIdx.x;
    __shared__ float red[256];
    __shared__ float ex[2048];

    float m = -INFINITY;
    for (int c = tid; c < S; c += 256) m = fmaxf(m, p[c]);
    red[tid] = m; __syncthreads();
    for (int o = 128; o > 0; o >>= 1) {
        if (tid < o) red[tid] = fmaxf(red[tid], red[tid + o]);
        __syncthreads();
    }
    m = red[0];
    __syncthreads();

    float sum = 0.f;
    for (int c = tid; c < S; c += 256) {
        const float e = expf(p[c] - m);
        ex[c] = e;
        sum += e;
    }
    red[tid] = sum; __syncthreads();
    for (int o = 128; o > 0; o >>= 1) {
        if (tid < o) red[tid] += red[tid + o];
        __syncthreads();
    }
    const float inv = 1.f / red[0];
    for (int c = tid; c < S; c += 256) {
        const float v = ex[c] * inv;
        __half h, l;
        split_h(v, h, l);
        oh[c] = h;
        ol[c] = l;
    }
}

// ---------------- residual + LayerNorm (D=1024), optional fp16 split out ----------------
template<bool DO_SPLIT>
__global__ __launch_bounds__(256) void addln_kernel(
    const float* __restrict__ x, const float* __restrict__ y,
    const float* __restrict__ g, const float* __restrict__ b,
    float* __restrict__ out, __half* __restrict__ oh,
    __half* __restrict__ ol, int D)
{
    const long row = blockIdx.x;
    const float* xp = x + row * (long)D;
    const float* yp = y + row * (long)D;
    const int tid = threadIdx.x;

    float v[4];
    float s = 0.f, ss = 0.f;
    #pragma unroll
    for (int i = 0; i < 4; i++) {
        const int c = tid + i * 256;
        const float t = xp[c] + yp[c];
        v[i] = t; s += t; ss += t * t;
    }
    __shared__ float r1[256], r2[256];
    r1[tid] = s; r2[tid] = ss; __syncthreads();
    for (int o = 128; o > 0; o >>= 1) {
        if (tid < o) { r1[tid] += r1[tid + o]; r2[tid] += r2[tid + o]; }
        __syncthreads();
    }
    const float mean = r1[0] / (float)D;
    const float var  = r2[0] / (float)D - mean * mean;
    const float rs   = rsqrtf(var + 1e-5f);
    #pragma unroll
    for (int i = 0; i < 4; i++) {
        const int c = tid + i * 256;
        const float o = (v[i] - mean) * rs * g[c] + b[c];
        out[row * (long)D + c] = o;
        if (DO_SPLIT) {
            __half h, l;
            split_h(o, h, l);
            oh[row * (long)D + c] = h;
            ol[row * (long)D + c] = l;
        }
    }
}

extern "C" void kernel_launch(void* const* d_in, const int* in_sizes, int n_in,
                              void* d_out, int out_size)
{
    const float* x    = (const float*)d_in[0];
    const float* mask = (const float*)d_in[1];
    const float* w1   = (const float*)d_in[2];
    const float* b1   = (const float*)d_in[3];
    const float* w2   = (const float*)d_in[4];
    const float* b2   = (const float*)d_in[5];
    const float* g1   = (const float*)d_in[6];
    const float* bt1  = (const float*)d_in[7];
    const float* g2   = (const float*)d_in[8];
    const float* bt2  = (const float*)d_in[9];
    float* out = (float*)d_out;

    float *scores, *attn, *h, *ffn2;
    __half *Xh, *Xl, *XTh, *Ph, *Pl, *Hh, *Hl, *W1h, *W2h, *Fh, *Fl;
    cudaGetSymbolAddress((void**)&scores, g_scores);
    cudaGetSymbolAddress((void**)&attn,   g_attn);
    cudaGetSymbolAddress((void**)&h,      g_h);
    cudaGetSymbolAddress((void**)&ffn2,   g_ffn2);
    cudaGetSymbolAddress((void**)&Xh,  g_Xh);  cudaGetSymbolAddress((void**)&Xl,  g_Xl);
    cudaGetSymbolAddress((void**)&XTh, g_XTh);
    cudaGetSymbolAddress((void**)&Ph,  g_Ph);  cudaGetSymbolAddress((void**)&Pl,  g_Pl);
    cudaGetSymbolAddress((void**)&Hh,  g_Hh);  cudaGetSymbolAddress((void**)&Hl,  g_Hl);
    cudaGetSymbolAddress((void**)&W1h, g_W1h);
    cudaGetSymbolAddress((void**)&W2h, g_W2h);
    cudaGetSymbolAddress((void**)&Fh,  g_Fh);  cudaGetSymbolAddress((void**)&Fl,  g_Fl);

    cudaFuncSetAttribute(gemm_tc<1,false>, cudaFuncAttributeMaxDynamicSharedMemorySize, SMEM_SZ);
    cudaFuncSetAttribute(gemm_tc<0,false>, cudaFuncAttributeMaxDynamicSharedMemorySize, SMEM_SZ);
    cudaFuncSetAttribute(gemm_tc<2,true>,  cudaFuncAttributeMaxDynamicSharedMemorySize, SMEM_SZ);
    cudaFuncSetAttribute(gemm_tc<3,false>, cudaFuncAttributeMaxDynamicSharedMemorySize, SMEM_SZ);

    const int B = Bb, S = Ss, D = Dd, DFF = Ff;
    const float scale = 0.03125f;  // 1/sqrt(1024)
    const long nX = (long)B * S * D;

    // 0) splits / transposes of GEMM operands
    split_kernel<<<(unsigned)(nX / 4 / 256), 256>>>(x, Xh, Xl, nX);
    tsplit_kernel<<<dim3(D/32, S/32, B), dim3(32,8)>>>(x,  XTh, S, D, (long)S*D, (long)D*S);
    tsplit_kernel<<<dim3(DFF/32, D/32, 1), dim3(32,8)>>>(w1, W1h, D, DFF, 0, 0);
    tsplit_kernel<<<dim3(D/32, DFF/32, 1), dim3(32,8)>>>(w2, W2h, DFF, D, 0, 0);

    // 1) scores = (X X^T) * scale + mask   -> fp32
    gemm_tc<1,false><<<dim3(S/BN, S/BM, B), NTH, SMEM_SZ>>>(
        Xh, Xl, Xh, scores, nullptr, nullptr,
        S, S, D, (long)S*D, (long)S*D, (long)S*S, mask, (long)S, scale);

    // 2) softmax rows -> P split (fp16 hi/lo)
    softmax_kernel<<<B*S, 256>>>(scores, Ph, Pl, S);

    // 3) attn = P X  (B operand = X^T, K-major, hi only)  -> fp32
    gemm_tc<0,false><<<dim3(D/BN, S/BM, B), NTH, SMEM_SZ>>>(
        Ph, Pl, XTh, attn, nullptr, nullptr,
        S, D, S, (long)S*S, (long)D*S, (long)S*D, nullptr, 0, 1.f);

    // 4) h = LN1(x + attn)  (+ H split)
    addln_kernel<true><<<B*S, 256>>>(x, attn, g1, bt1, h, Hh, Hl, D);

    // 5) F = gelu(h @ w1 + b1)  -> fp16 split directly
    gemm_tc<2,true><<<dim3(DFF/BN, (B*S)/BM, 1), NTH, SMEM_SZ>>>(
        Hh, Hl, W1h, nullptr, Fh, Fl,
        B*S, DFF, D, 0, 0, 0, b1, 0, 1.f);

    // 6) ffn2 = F @ w2 + b2 -> fp32
    gemm_tc<3,false><<<dim3(D/BN, (B*S)/BM, 1), NTH, SMEM_SZ>>>(
        Fh, Fl, W2h, ffn2, nullptr, nullptr,
        B*S, D, DFF, 0, 0, 0, b2, 0, 1.f);

    // 7) out = LN2(h + ffn2)
    addln_kernel<false><<<B*S, 256>>>(h, ffn2, g2, bt2, out, nullptr, nullptr, D);
}

// round 5
// speedup vs baseline: 4.1659x; 1.1088x over previous
#include <cuda_runtime.h>
#include <cuda_fp16.h>
#include <math.h>
#include <stdint.h>

#define Bb 4
#define Ss 2048
#define Dd 1024
#define Ff 4096

// ---------------- scratch (device globals; no runtime allocation) ----------------
__device__ __align__(1024) float g_scores[(long)Bb*Ss*Ss];
__device__ __align__(1024) float g_attn  [(long)Bb*Ss*Dd];
__device__ __align__(1024) float g_h     [(long)Bb*Ss*Dd];
__device__ __align__(1024) float g_ffn2  [(long)Bb*Ss*Dd];
__device__ __align__(1024) __half g_Xh [(long)Bb*Ss*Dd], g_Xl [(long)Bb*Ss*Dd];
__device__ __align__(1024) __half g_XTh[(long)Bb*Dd*Ss];
__device__ __align__(1024) __half g_Ph [(long)Bb*Ss*Ss], g_Pl [(long)Bb*Ss*Ss];
__device__ __align__(1024) __half g_Hh [(long)Bb*Ss*Dd], g_Hl [(long)Bb*Ss*Dd];
__device__ __align__(1024) __half g_W1h[(long)Ff*Dd];
__device__ __align__(1024) __half g_W2h[(long)Dd*Ff];
__device__ __align__(1024) __half g_Fh [(long)Bb*Ss*Ff], g_Fl [(long)Bb*Ss*Ff];

// ---------------- GEMM tiling ----------------
#define BM 128
#define BN 128
#define BK 32            // fp16 elems per k-chunk; 64 bytes per smem row
#define NTH 256
#define STAGES 3

#define OFF_AH 0
#define OFF_AL (BM*64)
#define OFF_BH (2*BM*64)
#define STAGE_BYTES (3*BM*64)            // 24576
#define SMEM_SZ (STAGES*STAGE_BYTES)     // 73728

// ---------------- PTX helpers (baseline ISA only) ----------------
__device__ __forceinline__ uint32_t swz(uint32_t o) { return o ^ ((o >> 3) & 0x30); }

__device__ __forceinline__ void cp16(uint32_t s, const void* g) {
    asm volatile("cp.async.cg.shared.global [%0], [%1], 16;" :: "r"(s), "l"(g));
}

__device__ __forceinline__ void ldm4(uint32_t* r, uint32_t a) {
    asm volatile("ldmatrix.sync.aligned.m8n8.x4.shared.b16 {%0,%1,%2,%3}, [%4];"
        : "=r"(r[0]), "=r"(r[1]), "=r"(r[2]), "=r"(r[3]) : "r"(a));
}

__device__ __forceinline__ void mma16816(float* c, const uint32_t* a, const uint32_t* b) {
    asm volatile(
        "mma.sync.aligned.m16n8k16.row.col.f32.f16.f16.f32 "
        "{%0,%1,%2,%3},{%4,%5,%6,%7},{%8,%9},{%0,%1,%2,%3};"
        : "+f"(c[0]), "+f"(c[1]), "+f"(c[2]), "+f"(c[3])
        : "r"(a[0]), "r"(a[1]), "r"(a[2]), "r"(a[3]), "r"(b[0]), "r"(b[1]));
}

// ---------------- stage loader: 6 x cp.async(16B) per thread ----------------
__device__ __forceinline__ void load_stage(
    uint32_t sb,
    const __half* __restrict__ Ah, const __half* __restrict__ Al,
    const __half* __restrict__ Bh,
    int tid, int m0, int n0, int K, int k0)
{
    const int row = tid >> 1;
    const int cb  = (tid & 1) * 32;           // byte col within 64B row
    const uint32_t so = (uint32_t)row * 64u + (uint32_t)cb;
    const char* ga_h = (const char*)(Ah + (long)(m0 + row) * K + k0) + cb;
    const char* ga_l = (const char*)(Al + (long)(m0 + row) * K + k0) + cb;
    const char* gb_h = (const char*)(Bh + (long)(n0 + row) * K + k0) + cb;
    cp16(sb + OFF_AH + swz(so),      ga_h);
    cp16(sb + OFF_AH + swz(so + 16), ga_h + 16);
    cp16(sb + OFF_AL + swz(so),      ga_l);
    cp16(sb + OFF_AL + swz(so + 16), ga_l + 16);
    cp16(sb + OFF_BH + swz(so),      gb_h);
    cp16(sb + OFF_BH + swz(so + 16), gb_h + 16);
}

__device__ __forceinline__ void split_h(float v, __half& hi, __half& lo) {
    hi = __float2half_rn(v);
    lo = __float2half_rn(v - __half2float(hi));
}

// EPI: 0 plain fp32, 1 acc*scale+mask[col] fp32, 2 gelu(acc+bias[col])->fp16 split, 3 acc+bias[col] fp32
// SYM: compute only lower-triangular tiles (m0>=n0), mirror-write upper half (requires EPI==1)
template<int EPI, bool SPLIT_OUT, bool SYM>
__global__ __launch_bounds__(NTH, 2)
void gemm_tc(
    const __half* __restrict__ Ah, const __half* __restrict__ Al,
    const __half* __restrict__ Bh,
    float* __restrict__ C, __half* __restrict__ Ch, __half* __restrict__ Cl,
    int M, int N, int K, long sA, long sB, long sC,
    const float* __restrict__ aux, long sAux, float scale)
{
    const int m0 = blockIdx.y * BM, n0 = blockIdx.x * BN;
    if (SYM && m0 < n0) return;

    extern __shared__ char dsm[];
    const uint32_t data = (uint32_t)__cvta_generic_to_shared(dsm);

    const int tid = threadIdx.x, wid = tid >> 5, lane = tid & 31;
    const int wm = wid >> 1;        // 0..3 -> M
    const int wn = wid & 1;         // 0..1 -> N
    const int bz = blockIdx.z;
    Ah += bz * sA; Al += bz * sA;
    Bh += bz * sB;

    float acc[2][8][4];
    #pragma unroll
    for (int i = 0; i < 2; i++)
        #pragma unroll
        for (int j = 0; j < 8; j++)
            #pragma unroll
            for (int q = 0; q < 4; q++) acc[i][j][q] = 0.f;

    const int nch = K / BK;
    load_stage(data, Ah, Al, Bh, tid, m0, n0, K, 0);
    asm volatile("cp.async.commit_group;");
    load_stage(data + STAGE_BYTES, Ah, Al, Bh, tid, m0, n0, K, BK);
    asm volatile("cp.async.commit_group;");

    int sidx = 0;
    for (int i = 0; i < nch; i++) {
        if (i + 1 < nch) asm volatile("cp.async.wait_group 1;");
        else             asm volatile("cp.async.wait_group 0;");
        __syncthreads();

        if (i + 2 < nch) {
            const int s2 = (i + 2) % STAGES;
            load_stage(data + (uint32_t)s2 * STAGE_BYTES, Ah, Al, Bh, tid, m0, n0, K, (i + 2) * BK);
            asm volatile("cp.async.commit_group;");
        }

        const uint32_t sb = data + (uint32_t)sidx * STAGE_BYTES;
        sidx = (sidx + 1 == STAGES) ? 0 : sidx + 1;

        #pragma unroll
        for (int k16 = 0; k16 < 2; k16++) {
            uint32_t ah[2][4], al[2][4], bh[4][4];
            const uint32_t arow = (uint32_t)(wm * 32 + (lane & 15));
            const uint32_t acol = (uint32_t)(k16 * 32 + (lane >> 4) * 16);
            ldm4(ah[0], sb + OFF_AH + swz(arow * 64 + acol));
            ldm4(ah[1], sb + OFF_AH + swz((arow + 16) * 64 + acol));
            ldm4(al[0], sb + OFF_AL + swz(arow * 64 + acol));
            ldm4(al[1], sb + OFF_AL + swz((arow + 16) * 64 + acol));
            const uint32_t brow = (uint32_t)(wn * 64 + (lane & 7) + (lane >> 4) * 8);
            const uint32_t bcol = (uint32_t)(k16 * 32 + ((lane >> 3) & 1) * 16);
            #pragma unroll
            for (int j = 0; j < 4; j++)
                ldm4(bh[j], sb + OFF_BH + swz((brow + j * 16) * 64 + bcol));

            #pragma unroll
            for (int mi = 0; mi < 2; mi++)
                #pragma unroll
                for (int nj = 0; nj < 8; nj++) {
                    const uint32_t* bhp = &bh[nj >> 1][(nj & 1) * 2];
                    mma16816(acc[mi][nj], ah[mi], bhp);
                    mma16816(acc[mi][nj], al[mi], bhp);
                }
        }
    }
    __syncthreads();

    // ---------------- epilogue from register accumulators ----------------
    const float* auxp = (EPI != 0) ? (aux + bz * sAux) : nullptr;
    if (!SPLIT_OUT && C) C += bz * sC;
    if (SPLIT_OUT) { Ch += bz * sC; Cl += bz * sC; }

    #pragma unroll
    for (int mi = 0; mi < 2; mi++) {
        const int r0 = m0 + wm * 32 + mi * 16 + (lane >> 2);
        float mr0 = 0.f, mr8 = 0.f;
        if (SYM) { mr0 = __ldg(&auxp[r0]); mr8 = __ldg(&auxp[r0 + 8]); }
        #pragma unroll
        for (int nj = 0; nj < 8; nj++) {
            const int c0 = n0 + wn * 64 + nj * 8 + (lane & 3) * 2;
            float v[4] = { acc[mi][nj][0], acc[mi][nj][1], acc[mi][nj][2], acc[mi][nj][3] };
            if (SYM) {
                // EPI==1 semantics: raw = acc*scale; C[r,c]=raw+mask[c]; mirror C[c,r]=raw+mask[r]
                const float mc0 = __ldg(&auxp[c0]);
                const float mc1 = __ldg(&auxp[c0 + 1]);
                float raw[4];
                #pragma unroll
                for (int q = 0; q < 4; q++) raw[q] = v[q] * scale;
                float2 lo; lo.x = raw[0] + mc0; lo.y = raw[1] + mc1;
                float2 hi; hi.x = raw[2] + mc0; hi.y = raw[3] + mc1;
                *reinterpret_cast<float2*>(C + (long)r0 * N + c0)       = lo;
                *reinterpret_cast<float2*>(C + (long)(r0 + 8) * N + c0) = hi;
                C[(long)c0 * N + r0]           = raw[0] + mr0;
                C[(long)(c0 + 1) * N + r0]     = raw[1] + mr0;
                C[(long)c0 * N + r0 + 8]       = raw[2] + mr8;
                C[(long)(c0 + 1) * N + r0 + 8] = raw[3] + mr8;
                continue;
            }
            #pragma unroll
            for (int q = 0; q < 4; q++) {
                const int col = c0 + (q & 1);
                float a = v[q];
                if (EPI == 1)      a = a * scale + __ldg(&auxp[col]);
                else if (EPI == 2) { a += __ldg(&auxp[col]);
                                     a = 0.5f * a * (1.0f + erff(a * 0.70710678118654752f)); }
                else if (EPI == 3) a += __ldg(&auxp[col]);
                v[q] = a;
            }
            if (!SPLIT_OUT) {
                float2 lo; lo.x = v[0]; lo.y = v[1];
                float2 hi; hi.x = v[2]; hi.y = v[3];
                *reinterpret_cast<float2*>(C + (long)r0 * N + c0)       = lo;
                *reinterpret_cast<float2*>(C + (long)(r0 + 8) * N + c0) = hi;
            } else {
                __half2 h01, h23, l01, l23;
                split_h(v[0], h01.x, l01.x);
                split_h(v[1], h01.y, l01.y);
                split_h(v[2], h23.x, l23.x);
                split_h(v[3], h23.y, l23.y);
                *reinterpret_cast<__half2*>(Ch + (long)r0 * N + c0)       = h01;
                *reinterpret_cast<__half2*>(Ch + (long)(r0 + 8) * N + c0) = h23;
                *reinterpret_cast<__half2*>(Cl + (long)r0 * N + c0)       = l01;
                *reinterpret_cast<__half2*>(Cl + (long)(r0 + 8) * N + c0) = l23;
            }
        }
    }
}

// ---------------- elementwise split: fp32 -> fp16 hi/lo ----------------
__global__ __launch_bounds__(256) void split_kernel(
    const float* __restrict__ in, __half* __restrict__ oh,
    __half* __restrict__ ol, long n)
{
    long i = ((long)blockIdx.x * blockDim.x + threadIdx.x) * 4;
    if (i >= n) return;
    float4 x = *reinterpret_cast<const float4*>(in + i);
    float vv[4] = { x.x, x.y, x.z, x.w };
    __half2 h01, h23, l01, l23;
    split_h(vv[0], h01.x, l01.x);
    split_h(vv[1], h01.y, l01.y);
    split_h(vv[2], h23.x, l23.x);
    split_h(vv[3], h23.y, l23.y);
    *reinterpret_cast<__half2*>(oh + i)     = h01;
    *reinterpret_cast<__half2*>(oh + i + 2) = h23;
    *reinterpret_cast<__half2*>(ol + i)     = l01;
    *reinterpret_cast<__half2*>(ol + i + 2) = l23;
}

// ---------------- transpose: fp32 [R,C] -> fp16 hi [C,R] ----------------
__global__ __launch_bounds__(256) void tsplit_kernel(
    const float* __restrict__ in, __half* __restrict__ oh,
    int R, int C, long sIn, long sOut)
{
    __shared__ float t[32][33];
    in += blockIdx.z * sIn; oh += blockIdx.z * sOut;
    const int c0 = blockIdx.x * 32, r0 = blockIdx.y * 32;
    const int tx = threadIdx.x, ty = threadIdx.y;  // 32 x 8
    #pragma unroll
    for (int k = 0; k < 4; k++)
        t[ty + 8*k][tx] = in[(long)(r0 + ty + 8*k) * C + c0 + tx];
    __syncthreads();
    #pragma unroll
    for (int k = 0; k < 4; k++) {
        const float v = t[tx][ty + 8*k];
        oh[(long)(c0 + ty + 8*k) * R + r0 + tx] = __float2half_rn(v);
    }
}

// ---------------- row softmax over S cols; writes fp16 hi/lo split ----------------
__global__ __launch_bounds__(256) void softmax_kernel(
    const float* __restrict__ s, __half* __restrict__ ph,
    __half* __restrict__ pl, int S)
{
    const long row = blockIdx.x;
    const float* p = s + row * (long)S;
    __half* oh = ph + row * (long)S;
    __half* ol = pl + row * (long)S;
    const int tid = threadIdx.x;
    __shared__ float red[256];
    __shared__ float ex[2048];

    float m = -INFINITY;
    for (int c = tid; c < S; c += 256) m = fmaxf(m, p[c]);
    red[tid] = m; __syncthreads();
    for (int o = 128; o > 0; o >>= 1) {
        if (tid < o) red[tid] = fmaxf(red[tid], red[tid + o]);
        __syncthreads();
    }
    m = red[0];
    __syncthreads();

    float sum = 0.f;
    for (int c = tid; c < S; c += 256) {
        const float e = expf(p[c] - m);
        ex[c] = e;
        sum += e;
    }
    red[tid] = sum; __syncthreads();
    for (int o = 128; o > 0; o >>= 1) {
        if (tid < o) red[tid] += red[tid + o];
        __syncthreads();
    }
    const float inv = 1.f / red[0];
    for (int c = tid; c < S; c += 256) {
        const float v = ex[c] * inv;
        __half h, l;
        split_h(v, h, l);
        oh[c] = h;
        ol[c] = l;
    }
}

// ---------------- residual + LayerNorm (D=1024), optional fp16 split out ----------------
template<bool DO_SPLIT>
__global__ __launch_bounds__(256) void addln_kernel(
    const float* __restrict__ x, const float* __restrict__ y,
    const float* __restrict__ g, const float* __restrict__ b,
    float* __restrict__ out, __half* __restrict__ oh,
    __half* __restrict__ ol, int D)
{
    const long row = blockIdx.x;
    const float* xp = x + row * (long)D;
    const float* yp = y + row * (long)D;
    const int tid = threadIdx.x;

    float v[4];
    float s = 0.f, ss = 0.f;
    #pragma unroll
    for (int i = 0; i < 4; i++) {
        const int c = tid + i * 256;
        const float t = xp[c] + yp[c];
        v[i] = t; s += t; ss += t * t;
    }
    __shared__ float r1[256], r2[256];
    r1[tid] = s; r2[tid] = ss; __syncthreads();
    for (int o = 128; o > 0; o >>= 1) {
        if (tid < o) { r1[tid] += r1[tid + o]; r2[tid] += r2[tid + o]; }
        __syncthreads();
    }
    const float mean = r1[0] / (float)D;
    const float var  = r2[0] / (float)D - mean * mean;
    const float rs   = rsqrtf(var + 1e-5f);
    #pragma unroll
    for (int i = 0; i < 4; i++) {
        const int c = tid + i * 256;
        const float o = (v[i] - mean) * rs * g[c] + b[c];
        out[row * (long)D + c] = o;
        if (DO_SPLIT) {
            __half h, l;
            split_h(o, h, l);
            oh[row * (long)D + c] = h;
            ol[row * (long)D + c] = l;
        }
    }
}

extern "C" void kernel_launch(void* const* d_in, const int* in_sizes, int n_in,
                              void* d_out, int out_size)
{
    const float* x    = (const float*)d_in[0];
    const float* mask = (const float*)d_in[1];
    const float* w1   = (const float*)d_in[2];
    const float* b1   = (const float*)d_in[3];
    const float* w2   = (const float*)d_in[4];
    const float* b2   = (const float*)d_in[5];
    const float* g1   = (const float*)d_in[6];
    const float* bt1  = (const float*)d_in[7];
    const float* g2   = (const float*)d_in[8];
    const float* bt2  = (const float*)d_in[9];
    float* out = (float*)d_out;

    float *scores, *attn, *h, *ffn2;
    __half *Xh, *Xl, *XTh, *Ph, *Pl, *Hh, *Hl, *W1h, *W2h, *Fh, *Fl;
    cudaGetSymbolAddress((void**)&scores, g_scores);
    cudaGetSymbolAddress((void**)&attn,   g_attn);
    cudaGetSymbolAddress((void**)&h,      g_h);
    cudaGetSymbolAddress((void**)&ffn2,   g_ffn2);
    cudaGetSymbolAddress((void**)&Xh,  g_Xh);  cudaGetSymbolAddress((void**)&Xl,  g_Xl);
    cudaGetSymbolAddress((void**)&XTh, g_XTh);
    cudaGetSymbolAddress((void**)&Ph,  g_Ph);  cudaGetSymbolAddress((void**)&Pl,  g_Pl);
    cudaGetSymbolAddress((void**)&Hh,  g_Hh);  cudaGetSymbolAddress((void**)&Hl,  g_Hl);
    cudaGetSymbolAddress((void**)&W1h, g_W1h);
    cudaGetSymbolAddress((void**)&W2h, g_W2h);
    cudaGetSymbolAddress((void**)&Fh,  g_Fh);  cudaGetSymbolAddress((void**)&Fl,  g_Fl);

    cudaFuncSetAttribute(gemm_tc<1,false,true>,  cudaFuncAttributeMaxDynamicSharedMemorySize, SMEM_SZ);
    cudaFuncSetAttribute(gemm_tc<0,false,false>, cudaFuncAttributeMaxDynamicSharedMemorySize, SMEM_SZ);
    cudaFuncSetAttribute(gemm_tc<2,true,false>,  cudaFuncAttributeMaxDynamicSharedMemorySize, SMEM_SZ);
    cudaFuncSetAttribute(gemm_tc<3,false,false>, cudaFuncAttributeMaxDynamicSharedMemorySize, SMEM_SZ);

    const int B = Bb, S = Ss, D = Dd, DFF = Ff;
    const float scale = 0.03125f;  // 1/sqrt(1024)
    const long nX = (long)B * S * D;

    // 0) splits / transposes of GEMM operands
    split_kernel<<<(unsigned)(nX / 4 / 256), 256>>>(x, Xh, Xl, nX);
    tsplit_kernel<<<dim3(D/32, S/32, B), dim3(32,8)>>>(x,  XTh, S, D, (long)S*D, (long)D*S);
    tsplit_kernel<<<dim3(DFF/32, D/32, 1), dim3(32,8)>>>(w1, W1h, D, DFF, 0, 0);
    tsplit_kernel<<<dim3(D/32, DFF/32, 1), dim3(32,8)>>>(w2, W2h, DFF, D, 0, 0);

    // 1) scores = (X X^T) * scale + mask  (symmetric: lower tiles only, mirrored)
    gemm_tc<1,false,true><<<dim3(S/BN, S/BM, B), NTH, SMEM_SZ>>>(
        Xh, Xl, Xh, scores, nullptr, nullptr,
        S, S, D, (long)S*D, (long)S*D, (long)S*S, mask, (long)S, scale);

    // 2) softmax rows -> P split (fp16 hi/lo)
    softmax_kernel<<<B*S, 256>>>(scores, Ph, Pl, S);

    // 3) attn = P X  (B operand = X^T, K-major, hi only)  -> fp32
    gemm_tc<0,false,false><<<dim3(D/BN, S/BM, B), NTH, SMEM_SZ>>>(
        Ph, Pl, XTh, attn, nullptr, nullptr,
        S, D, S, (long)S*S, (long)D*S, (long)S*D, nullptr, 0, 1.f);

    // 4) h = LN1(x + attn)  (+ H split)
    addln_kernel<true><<<B*S, 256>>>(x, attn, g1, bt1, h, Hh, Hl, D);

    // 5) F = gelu(h @ w1 + b1)  -> fp16 split directly
    gemm_tc<2,true,false><<<dim3(DFF/BN, (B*S)/BM, 1), NTH, SMEM_SZ>>>(
        Hh, Hl, W1h, nullptr, Fh, Fl,
        B*S, DFF, D, 0, 0, 0, b1, 0, 1.f);

    // 6) ffn2 = F @ w2 + b2 -> fp32
    gemm_tc<3,false,false><<<dim3(D/BN, (B*S)/BM, 1), NTH, SMEM_SZ>>>(
        Fh, Fl, W2h, ffn2, nullptr, nullptr,
        B*S, D, DFF, 0, 0, 0, b2, 0, 1.f);

    // 7) out = LN2(h + ffn2)
    addln_kernel<false><<<B*S, 256>>>(h, ffn2, g2, bt2, out, nullptr, nullptr, D);
}

// round 6
// speedup vs baseline: 6.6451x; 1.5951x over previous
#include <cuda_runtime.h>
#include <cuda_fp16.h>
#include <math.h>
#include <stdint.h>

#define Bb 4
#define Ss 2048
#define Dd 1024
#define Ff 4096

// ---------------- scratch (device globals; no runtime allocation) ----------------
__device__ __align__(1024) float g_scores[(long)Bb*Ss*Ss];
__device__ __align__(1024) float g_attn  [(long)Bb*Ss*Dd];
__device__ __align__(1024) float g_h     [(long)Bb*Ss*Dd];
__device__ __align__(1024) float g_ffn2  [(long)Bb*Ss*Dd];
__device__ __align__(1024) __half g_Xh [(long)Bb*Ss*Dd];
__device__ __align__(1024) __half g_XTh[(long)Bb*Dd*Ss];
__device__ __align__(1024) __half g_Ph [(long)Bb*Ss*Ss];
__device__ __align__(1024) __half g_Hh [(long)Bb*Ss*Dd];
__device__ __align__(1024) __half g_W1h[(long)Ff*Dd];
__device__ __align__(1024) __half g_W2h[(long)Dd*Ff];
__device__ __align__(1024) __half g_Fh [(long)Bb*Ss*Ff];

// ---------------- GEMM tiling ----------------
#define BM 128
#define BN 128
#define BK 32            // fp16 elems per k-chunk; 64 bytes per smem row
#define NTH 256
#define STAGES 4

#define OFF_A 0
#define OFF_B (BM*64)
#define STAGE_BYTES (2*BM*64)            // 16384
#define SMEM_SZ (STAGES*STAGE_BYTES)     // 65536

// ---------------- PTX helpers (baseline ISA only) ----------------
__device__ __forceinline__ uint32_t swz(uint32_t o) { return o ^ ((o >> 3) & 0x30); }

__device__ __forceinline__ void cp16(uint32_t s, const void* g) {
    asm volatile("cp.async.cg.shared.global [%0], [%1], 16;" :: "r"(s), "l"(g));
}

__device__ __forceinline__ void ldm4(uint32_t* r, uint32_t a) {
    asm volatile("ldmatrix.sync.aligned.m8n8.x4.shared.b16 {%0,%1,%2,%3}, [%4];"
        : "=r"(r[0]), "=r"(r[1]), "=r"(r[2]), "=r"(r[3]) : "r"(a));
}

__device__ __forceinline__ void mma16816(float* c, const uint32_t* a, const uint32_t* b) {
    asm volatile(
        "mma.sync.aligned.m16n8k16.row.col.f32.f16.f16.f32 "
        "{%0,%1,%2,%3},{%4,%5,%6,%7},{%8,%9},{%0,%1,%2,%3};"
        : "+f"(c[0]), "+f"(c[1]), "+f"(c[2]), "+f"(c[3])
        : "r"(a[0]), "r"(a[1]), "r"(a[2]), "r"(a[3]), "r"(b[0]), "r"(b[1]));
}

// ---------------- stage loader: 4 x cp.async(16B) per thread ----------------
__device__ __forceinline__ void load_stage(
    uint32_t sb,
    const __half* __restrict__ A, const __half* __restrict__ B,
    int tid, int m0, int n0, int K, int k0)
{
    const int row = tid >> 1;
    const int cb  = (tid & 1) * 32;           // byte col within 64B row
    const uint32_t so = (uint32_t)row * 64u + (uint32_t)cb;
    const char* ga = (const char*)(A + (long)(m0 + row) * K + k0) + cb;
    const char* gb = (const char*)(B + (long)(n0 + row) * K + k0) + cb;
    cp16(sb + OFF_A + swz(so),      ga);
    cp16(sb + OFF_A + swz(so + 16), ga + 16);
    cp16(sb + OFF_B + swz(so),      gb);
    cp16(sb + OFF_B + swz(so + 16), gb + 16);
}

// EPI: 0 plain fp32, 1 acc*scale+mask[col] fp32 (+SYM mirror), 2 gelu(acc+bias[col])->fp16, 3 acc+bias[col] fp32
template<int EPI, bool HALF_OUT, bool SYM>
__global__ __launch_bounds__(NTH, 2)
void gemm_tc(
    const __half* __restrict__ A, const __half* __restrict__ B,
    float* __restrict__ C, __half* __restrict__ Ch,
    int M, int N, int K, long sA, long sB, long sC,
    const float* __restrict__ aux, long sAux, float scale)
{
    const int m0 = blockIdx.y * BM, n0 = blockIdx.x * BN;
    if (SYM && m0 < n0) return;

    extern __shared__ char dsm[];
    const uint32_t data = (uint32_t)__cvta_generic_to_shared(dsm);

    const int tid = threadIdx.x, wid = tid >> 5, lane = tid & 31;
    const int wm = wid >> 1;        // 0..3 -> M
    const int wn = wid & 1;         // 0..1 -> N
    const int bz = blockIdx.z;
    A += bz * sA;
    B += bz * sB;

    float acc[2][8][4];
    #pragma unroll
    for (int i = 0; i < 2; i++)
        #pragma unroll
        for (int j = 0; j < 8; j++)
            #pragma unroll
            for (int q = 0; q < 4; q++) acc[i][j][q] = 0.f;

    const int nch = K / BK;
    load_stage(data, A, B, tid, m0, n0, K, 0);
    asm volatile("cp.async.commit_group;");
    load_stage(data + STAGE_BYTES, A, B, tid, m0, n0, K, BK);
    asm volatile("cp.async.commit_group;");
    load_stage(data + 2 * STAGE_BYTES, A, B, tid, m0, n0, K, 2 * BK);
    asm volatile("cp.async.commit_group;");

    int sidx = 0;
    for (int i = 0; i < nch; i++) {
        if (i + 3 <= nch)      asm volatile("cp.async.wait_group 2;");
        else if (i + 2 == nch) asm volatile("cp.async.wait_group 1;");
        else                   asm volatile("cp.async.wait_group 0;");
        __syncthreads();

        if (i + 3 < nch) {
            const int s2 = (i + 3) & (STAGES - 1);
            load_stage(data + (uint32_t)s2 * STAGE_BYTES, A, B, tid, m0, n0, K, (i + 3) * BK);
            asm volatile("cp.async.commit_group;");
        }

        const uint32_t sb = data + (uint32_t)sidx * STAGE_BYTES;
        sidx = (sidx + 1) & (STAGES - 1);

        #pragma unroll
        for (int k16 = 0; k16 < 2; k16++) {
            uint32_t ah[2][4], bh[4][4];
            const uint32_t arow = (uint32_t)(wm * 32 + (lane & 15));
            const uint32_t acol = (uint32_t)(k16 * 32 + (lane >> 4) * 16);
            ldm4(ah[0], sb + OFF_A + swz(arow * 64 + acol));
            ldm4(ah[1], sb + OFF_A + swz((arow + 16) * 64 + acol));
            const uint32_t brow = (uint32_t)(wn * 64 + (lane & 7) + (lane >> 4) * 8);
            const uint32_t bcol = (uint32_t)(k16 * 32 + ((lane >> 3) & 1) * 16);
            #pragma unroll
            for (int j = 0; j < 4; j++)
                ldm4(bh[j], sb + OFF_B + swz((brow + j * 16) * 64 + bcol));

            #pragma unroll
            for (int mi = 0; mi < 2; mi++)
                #pragma unroll
                for (int nj = 0; nj < 8; nj++)
                    mma16816(acc[mi][nj], ah[mi], &bh[nj >> 1][(nj & 1) * 2]);
        }
    }
    __syncthreads();

    // ---------------- epilogue from register accumulators ----------------
    const float* auxp = (EPI != 0) ? (aux + bz * sAux) : nullptr;
    if (!HALF_OUT && C) C += bz * sC;
    if (HALF_OUT) Ch += bz * sC;

    #pragma unroll
    for (int mi = 0; mi < 2; mi++) {
        const int r0 = m0 + wm * 32 + mi * 16 + (lane >> 2);
        float mr0 = 0.f, mr8 = 0.f;
        if (SYM) { mr0 = __ldg(&auxp[r0]); mr8 = __ldg(&auxp[r0 + 8]); }
        #pragma unroll
        for (int nj = 0; nj < 8; nj++) {
            const int c0 = n0 + wn * 64 + nj * 8 + (lane & 3) * 2;
            float v[4] = { acc[mi][nj][0], acc[mi][nj][1], acc[mi][nj][2], acc[mi][nj][3] };
            if (SYM) {
                const float mc0 = __ldg(&auxp[c0]);
                const float mc1 = __ldg(&auxp[c0 + 1]);
                float raw[4];
                #pragma unroll
                for (int q = 0; q < 4; q++) raw[q] = v[q] * scale;
                float2 lo; lo.x = raw[0] + mc0; lo.y = raw[1] + mc1;
                float2 hi; hi.x = raw[2] + mc0; hi.y = raw[3] + mc1;
                *reinterpret_cast<float2*>(C + (long)r0 * N + c0)       = lo;
                *reinterpret_cast<float2*>(C + (long)(r0 + 8) * N + c0) = hi;
                C[(long)c0 * N + r0]           = raw[0] + mr0;
                C[(long)(c0 + 1) * N + r0]     = raw[1] + mr0;
                C[(long)c0 * N + r0 + 8]       = raw[2] + mr8;
                C[(long)(c0 + 1) * N + r0 + 8] = raw[3] + mr8;
                continue;
            }
            #pragma unroll
            for (int q = 0; q < 4; q++) {
                const int col = c0 + (q & 1);
                float a = v[q];
                if (EPI == 1)      a = a * scale + __ldg(&auxp[col]);
                else if (EPI == 2) { a += __ldg(&auxp[col]);
                                     a = 0.5f * a * (1.0f + erff(a * 0.70710678118654752f)); }
                else if (EPI == 3) a += __ldg(&auxp[col]);
                v[q] = a;
            }
            if (!HALF_OUT) {
                float2 lo; lo.x = v[0]; lo.y = v[1];
                float2 hi; hi.x = v[2]; hi.y = v[3];
                *reinterpret_cast<float2*>(C + (long)r0 * N + c0)       = lo;
                *reinterpret_cast<float2*>(C + (long)(r0 + 8) * N + c0) = hi;
            } else {
                __half2 h01, h23;
                h01.x = __float2half_rn(v[0]); h01.y = __float2half_rn(v[1]);
                h23.x = __float2half_rn(v[2]); h23.y = __float2half_rn(v[3]);
                *reinterpret_cast<__half2*>(Ch + (long)r0 * N + c0)       = h01;
                *reinterpret_cast<__half2*>(Ch + (long)(r0 + 8) * N + c0) = h23;
            }
        }
    }
}

// ---------------- elementwise convert: fp32 -> fp16 ----------------
__global__ __launch_bounds__(256) void cvt_kernel(
    const float* __restrict__ in, __half* __restrict__ oh, long n)
{
    long i = ((long)blockIdx.x * blockDim.x + threadIdx.x) * 4;
    if (i >= n) return;
    float4 x = *reinterpret_cast<const float4*>(in + i);
    __half2 h01, h23;
    h01.x = __float2half_rn(x.x); h01.y = __float2half_rn(x.y);
    h23.x = __float2half_rn(x.z); h23.y = __float2half_rn(x.w);
    *reinterpret_cast<__half2*>(oh + i)     = h01;
    *reinterpret_cast<__half2*>(oh + i + 2) = h23;
}

// ---------------- transpose: fp32 [R,C] -> fp16 [C,R] ----------------
__global__ __launch_bounds__(256) void tsplit_kernel(
    const float* __restrict__ in, __half* __restrict__ oh,
    int R, int C, long sIn, long sOut)
{
    __shared__ float t[32][33];
    in += blockIdx.z * sIn; oh += blockIdx.z * sOut;
    const int c0 = blockIdx.x * 32, r0 = blockIdx.y * 32;
    const int tx = threadIdx.x, ty = threadIdx.y;  // 32 x 8
    #pragma unroll
    for (int k = 0; k < 4; k++)
        t[ty + 8*k][tx] = in[(long)(r0 + ty + 8*k) * C + c0 + tx];
    __syncthreads();
    #pragma unroll
    for (int k = 0; k < 4; k++) {
        const float v = t[tx][ty + 8*k];
        oh[(long)(c0 + ty + 8*k) * R + r0 + tx] = __float2half_rn(v);
    }
}

// ---------------- row softmax over S cols; writes fp16 ----------------
__global__ __launch_bounds__(256) void softmax_kernel(
    const float* __restrict__ s, __half* __restrict__ ph, int S)
{
    const long row = blockIdx.x;
    const float* p = s + row * (long)S;
    __half* oh = ph + row * (long)S;
    const int tid = threadIdx.x;
    __shared__ float red[256];
    __shared__ float ex[2048];

    float m = -INFINITY;
    for (int c = tid; c < S; c += 256) m = fmaxf(m, p[c]);
    red[tid] = m; __syncthreads();
    for (int o = 128; o > 0; o >>= 1) {
        if (tid < o) red[tid] = fmaxf(red[tid], red[tid + o]);
        __syncthreads();
    }
    m = red[0];
    __syncthreads();

    float sum = 0.f;
    for (int c = tid; c < S; c += 256) {
        const float e = expf(p[c] - m);
        ex[c] = e;
        sum += e;
    }
    red[tid] = sum; __syncthreads();
    for (int o = 128; o > 0; o >>= 1) {
        if (tid < o) red[tid] += red[tid + o];
        __syncthreads();
    }
    const float inv = 1.f / red[0];
    for (int c = tid; c < S; c += 256)
        oh[c] = __float2half_rn(ex[c] * inv);
}

// ---------------- residual + LayerNorm (D=1024), optional fp16 out ----------------
template<bool DO_HALF>
__global__ __launch_bounds__(256) void addln_kernel(
    const float* __restrict__ x, const float* __restrict__ y,
    const float* __restrict__ g, const float* __restrict__ b,
    float* __restrict__ out, __half* __restrict__ oh, int D)
{
    const long row = blockIdx.x;
    const float* xp = x + row * (long)D;
    const float* yp = y + row * (long)D;
    const int tid = threadIdx.x;

    float v[4];
    float s = 0.f, ss = 0.f;
    #pragma unroll
    for (int i = 0; i < 4; i++) {
        const int c = tid + i * 256;
        const float t = xp[c] + yp[c];
        v[i] = t; s += t; ss += t * t;
    }
    __shared__ float r1[256], r2[256];
    r1[tid] = s; r2[tid] = ss; __syncthreads();
    for (int o = 128; o > 0; o >>= 1) {
        if (tid < o) { r1[tid] += r1[tid + o]; r2[tid] += r2[tid + o]; }
        __syncthreads();
    }
    const float mean = r1[0] / (float)D;
    const float var  = r2[0] / (float)D - mean * mean;
    const float rs   = rsqrtf(var + 1e-5f);
    #pragma unroll
    for (int i = 0; i < 4; i++) {
        const int c = tid + i * 256;
        const float o = (v[i] - mean) * rs * g[c] + b[c];
        out[row * (long)D + c] = o;
        if (DO_HALF) oh[row * (long)D + c] = __float2half_rn(o);
    }
}

extern "C" void kernel_launch(void* const* d_in, const int* in_sizes, int n_in,
                              void* d_out, int out_size)
{
    const float* x    = (const float*)d_in[0];
    const float* mask = (const float*)d_in[1];
    const float* w1   = (const float*)d_in[2];
    const float* b1   = (const float*)d_in[3];
    const float* w2   = (const float*)d_in[4];
    const float* b2   = (const float*)d_in[5];
    const float* g1   = (const float*)d_in[6];
    const float* bt1  = (const float*)d_in[7];
    const float* g2   = (const float*)d_in[8];
    const float* bt2  = (const float*)d_in[9];
    float* out = (float*)d_out;

    float *scores, *attn, *h, *ffn2;
    __half *Xh, *XTh, *Ph, *Hh, *W1h, *W2h, *Fh;
    cudaGetSymbolAddress((void**)&scores, g_scores);
    cudaGetSymbolAddress((void**)&attn,   g_attn);
    cudaGetSymbolAddress((void**)&h,      g_h);
    cudaGetSymbolAddress((void**)&ffn2,   g_ffn2);
    cudaGetSymbolAddress((void**)&Xh,  g_Xh);
    cudaGetSymbolAddress((void**)&XTh, g_XTh);
    cudaGetSymbolAddress((void**)&Ph,  g_Ph);
    cudaGetSymbolAddress((void**)&Hh,  g_Hh);
    cudaGetSymbolAddress((void**)&W1h, g_W1h);
    cudaGetSymbolAddress((void**)&W2h, g_W2h);
    cudaGetSymbolAddress((void**)&Fh,  g_Fh);

    cudaFuncSetAttribute(gemm_tc<1,false,true>,  cudaFuncAttributeMaxDynamicSharedMemorySize, SMEM_SZ);
    cudaFuncSetAttribute(gemm_tc<0,false,false>, cudaFuncAttributeMaxDynamicSharedMemorySize, SMEM_SZ);
    cudaFuncSetAttribute(gemm_tc<2,true,false>,  cudaFuncAttributeMaxDynamicSharedMemorySize, SMEM_SZ);
    cudaFuncSetAttribute(gemm_tc<3,false,false>, cudaFuncAttributeMaxDynamicSharedMemorySize, SMEM_SZ);

    const int B = Bb, S = Ss, D = Dd, DFF = Ff;
    const float scale = 0.03125f;  // 1/sqrt(1024)
    const long nX = (long)B * S * D;

    // 0) converts / transposes of GEMM operands
    cvt_kernel<<<(unsigned)(nX / 4 / 256), 256>>>(x, Xh, nX);
    tsplit_kernel<<<dim3(D/32, S/32, B), dim3(32,8)>>>(x,  XTh, S, D, (long)S*D, (long)D*S);
    tsplit_kernel<<<dim3(DFF/32, D/32, 1), dim3(32,8)>>>(w1, W1h, D, DFF, 0, 0);
    tsplit_kernel<<<dim3(D/32, DFF/32, 1), dim3(32,8)>>>(w2, W2h, DFF, D, 0, 0);

    // 1) scores = (X X^T) * scale + mask  (symmetric: lower tiles only, mirrored)
    gemm_tc<1,false,true><<<dim3(S/BN, S/BM, B), NTH, SMEM_SZ>>>(
        Xh, Xh, scores, nullptr,
        S, S, D, (long)S*D, (long)S*D, (long)S*S, mask, (long)S, scale);

    // 2) softmax rows -> P (fp16)
    softmax_kernel<<<B*S, 256>>>(scores, Ph, S);

    // 3) attn = P X  (B operand = X^T, K-major)  -> fp32
    gemm_tc<0,false,false><<<dim3(D/BN, S/BM, B), NTH, SMEM_SZ>>>(
        Ph, XTh, attn, nullptr,
        S, D, S, (long)S*S, (long)D*S, (long)S*D, nullptr, 0, 1.f);

    // 4) h = LN1(x + attn)  (+ fp16 copy)
    addln_kernel<true><<<B*S, 256>>>(x, attn, g1, bt1, h, Hh, D);

    // 5) F = gelu(h @ w1 + b1)  -> fp16 directly
    gemm_tc<2,true,false><<<dim3(DFF/BN, (B*S)/BM, 1), NTH, SMEM_SZ>>>(
        Hh, W1h, nullptr, Fh,
        B*S, DFF, D, 0, 0, 0, b1, 0, 1.f);

    // 6) ffn2 = F @ w2 + b2 -> fp32
    gemm_tc<3,false,false><<<dim3(D/BN, (B*S)/BM, 1), NTH, SMEM_SZ>>>(
        Fh, W2h, ffn2, nullptr,
        B*S, D, DFF, 0, 0, 0, b2, 0, 1.f);

    // 7) out = LN2(h + ffn2)
    addln_kernel<false><<<B*S, 256>>>(h, ffn2, g2, bt2, out, nullptr, D);
}